// round 8
// baseline (speedup 1.0000x reference)
#include <cuda_runtime.h>
#include <cstdint>
#include <cstddef>

// ============================ problem constants ============================
#define BATCH 16
#define SEQ   2048
#define DIMD  64
#define QT    128          // q rows per CTA
#define KT    64           // kv rows per tile
#define NKT   (SEQ / KT)   // 32
#define NB    (KT / 8)     // 8 n-blocks per tile
#define PITCH 68           // smem row pitch in floats (bank-conflict-free)
#define TILEF (KT * PITCH)         // floats per tile buffer (4352)
#define TILEB (TILEF * 4)          // bytes per tile buffer (17408)

#define K1_SMEM (3 * TILEB)        // score kernel: 3-deep K ring (52,224 B)
#define K2_SMEM (3 * TILEB)        // pv kernel:    3-deep V ring (52,224 B)

// ============================ device scratch ============================
__device__ float g_inv[(size_t)BATCH * SEQ];   // 1/rowsum per (b, q-row)

// ============================ helpers ============================
__device__ __forceinline__ uint32_t f2t(float f) {
    uint32_t u;
    asm("cvt.rna.tf32.f32 %0, %1;" : "=r"(u) : "f"(f));
    return u;
}
__device__ __forceinline__ uint32_t smem_u32(const void* p) {
    uint32_t a;
    asm("{ .reg .u64 t; cvta.to.shared.u64 t, %1; cvt.u32.u64 %0, t; }" : "=r"(a) : "l"(p));
    return a;
}
__device__ __forceinline__ void cpasync16(uint32_t dst, const float* src) {
    asm volatile("cp.async.cg.shared.global [%0], [%1], 16;" :: "r"(dst), "l"(src));
}
#define CP_COMMIT() asm volatile("cp.async.commit_group;" ::: "memory")
#define CP_WAIT(n)  asm volatile("cp.async.wait_group %0;" :: "n"(n) : "memory")

__device__ __forceinline__ void mma8(float& c0, float& c1, float& c2, float& c3,
                                     uint32_t a0, uint32_t a1, uint32_t a2, uint32_t a3,
                                     uint32_t b0, uint32_t b1) {
    asm volatile(
        "mma.sync.aligned.m16n8k8.row.col.f32.tf32.tf32.f32 "
        "{%0,%1,%2,%3},{%4,%5,%6,%7},{%8,%9},{%0,%1,%2,%3};"
        : "+f"(c0), "+f"(c1), "+f"(c2), "+f"(c3)
        : "r"(a0), "r"(a1), "r"(a2), "r"(a3), "r"(b0), "r"(b1));
}

// stage one 64x64 f32 tile (raw bits) into smem at pitch 272B via cp.async
__device__ __forceinline__ void ld_tile(uint32_t dst, const float* __restrict__ g, int tid) {
#pragma unroll
    for (int i = 0; i < 4; i++) {
        int idx = tid + i * 256;           // 1024 16B-chunks: 64 rows x 16
        int row = idx >> 4, c4 = idx & 15;
        cpasync16(dst + row * (PITCH * 4) + c4 * 16, g + row * DIMD + c4 * 4);
    }
}

// load this lane's Q fragments (single tf32, RN, pre-scaled by 1/8)
__device__ __forceinline__ void load_q_frags(uint32_t* qh, const float* __restrict__ Q,
                                             int b, int qr, int c) {
    const float* q0p = Q + ((size_t)b * SEQ + qr) * DIMD;
    const float* q1p = q0p + 8 * DIMD;
#pragma unroll
    for (int j = 0; j < 8; j++) {
        qh[4*j+0] = f2t(q0p[8 * j + c]     * 0.125f);
        qh[4*j+1] = f2t(q1p[8 * j + c]     * 0.125f);
        qh[4*j+2] = f2t(q0p[8 * j + c + 4] * 0.125f);
        qh[4*j+3] = f2t(q1p[8 * j + c + 4] * 0.125f);
    }
}

// ============================ kernel 1: scores + exp + rowsums ============================
// Writes UNNORMALIZED exp(scores) into attn_out (scratch; overwritten normalized by k2).
__global__ void __launch_bounds__(256, 4)
score_kernel(const float* __restrict__ Q, const float* __restrict__ K,
             float* __restrict__ attn_out)
{
    extern __shared__ float sm[];
    float* buf[3] = { sm, sm + TILEF, sm + 2 * TILEF };
    const uint32_t smb = smem_u32(sm);
    const uint32_t bd[3] = { smb, smb + TILEB, smb + 2 * TILEB };

    const int tid  = threadIdx.x;
    const int w    = tid >> 5;
    const int lane = tid & 31;
    const int r    = lane >> 2;
    const int c    = lane & 3;

    const int b  = blockIdx.x >> 4;
    const int q0 = (blockIdx.x & 15) << 7;
    const int qr = q0 + 16 * w + r;

    const float* Kb = K + (size_t)b * SEQ * DIMD;

    uint32_t qh[32];
    load_q_frags(qh, Q, b, qr, c);

    float rs0 = 0.f, rs1 = 0.f;
    ld_tile(bd[0], Kb, tid); CP_COMMIT();
    ld_tile(bd[1], Kb + (size_t)KT * DIMD, tid); CP_COMMIT();
    int bidx = 0;
    for (int t = 0; t < NKT; t++) {
        CP_WAIT(1);
        __syncthreads();
        if (t + 2 < NKT) {
            int nb2 = bidx + 2; if (nb2 >= 3) nb2 -= 3;
            ld_tile(bd[nb2], Kb + (size_t)(t + 2) * KT * DIMD, tid);
            CP_COMMIT();
        }
        const float* kh = buf[bidx];
        if (++bidx == 3) bidx = 0;

        float* a0p = attn_out + ((size_t)b * SEQ + qr) * SEQ + t * KT;
        float* a1p = a0p + (size_t)8 * SEQ;

#pragma unroll
        for (int nb = 0; nb < NB; nb++) {
            float e0 = 0.f, e1 = 0.f, e2 = 0.f, e3 = 0.f;
            float o0 = 0.f, o1 = 0.f, o2 = 0.f, o3 = 0.f;
            const int base = (nb * 8 + r) * PITCH + c;
#pragma unroll
            for (int j2 = 0; j2 < 4; j2++) {
                const int je = 2 * j2, jo = 2 * j2 + 1;
                // RN-round K fragments: these scores ARE the attn numerator
                uint32_t be0 = f2t(kh[base + 8 * je]);
                uint32_t be1 = f2t(kh[base + 8 * je + 4]);
                uint32_t bo0 = f2t(kh[base + 8 * jo]);
                uint32_t bo1 = f2t(kh[base + 8 * jo + 4]);
                mma8(e0, e1, e2, e3, qh[4*je], qh[4*je+1], qh[4*je+2], qh[4*je+3], be0, be1);
                mma8(o0, o1, o2, o3, qh[4*jo], qh[4*jo+1], qh[4*jo+2], qh[4*jo+3], bo0, bo1);
            }
            float p0 = __expf(e0 + o0);
            float p1 = __expf(e1 + o1);
            float p2 = __expf(e2 + o2);
            float p3 = __expf(e3 + o3);
            rs0 += p0 + p1;
            rs1 += p2 + p3;
            *(float2*)(a0p + nb * 8 + 2 * c) = make_float2(p0, p1);
            *(float2*)(a1p + nb * 8 + 2 * c) = make_float2(p2, p3);
        }
        __syncthreads();
    }
    rs0 += __shfl_xor_sync(0xFFFFFFFFu, rs0, 1);
    rs0 += __shfl_xor_sync(0xFFFFFFFFu, rs0, 2);
    rs1 += __shfl_xor_sync(0xFFFFFFFFu, rs1, 1);
    rs1 += __shfl_xor_sync(0xFFFFFFFFu, rs1, 2);
    if (c == 0) {
        g_inv[(size_t)b * SEQ + qr]     = 1.0f / rs0;
        g_inv[(size_t)b * SEQ + qr + 8] = 1.0f / rs1;
    }
}

// ============================ kernel 2: normalize attn + PV ============================
__global__ void __launch_bounds__(256, 3)
pv_kernel(const float* __restrict__ V, float* __restrict__ ctx_out,
          float* __restrict__ attn_out)
{
    extern __shared__ float sm[];
    float* buf[3] = { sm, sm + TILEF, sm + 2 * TILEF };
    const uint32_t smb = smem_u32(sm);
    const uint32_t bd[3] = { smb, smb + TILEB, smb + 2 * TILEB };

    const int tid  = threadIdx.x;
    const int w    = tid >> 5;
    const int lane = tid & 31;
    const int r    = lane >> 2;
    const int c    = lane & 3;

    const int b  = blockIdx.x >> 4;
    const int q0 = (blockIdx.x & 15) << 7;
    const int qr = q0 + 16 * w + r;

    const float* Vb = V + (size_t)b * SEQ * DIMD;

    ld_tile(bd[0], Vb, tid); CP_COMMIT();
    ld_tile(bd[1], Vb + (size_t)KT * DIMD, tid); CP_COMMIT();

    const float inv0 = g_inv[(size_t)b * SEQ + qr];
    const float inv1 = g_inv[(size_t)b * SEQ + qr + 8];

    float cx[32];
#pragma unroll
    for (int i = 0; i < 32; i++) cx[i] = 0.f;

    int bidx = 0;
    for (int t = 0; t < NKT; t++) {
        CP_WAIT(1);
        __syncthreads();
        if (t + 2 < NKT) {
            int nb2 = bidx + 2; if (nb2 >= 3) nb2 -= 3;
            ld_tile(bd[nb2], Vb + (size_t)(t + 2) * KT * DIMD, tid);
            CP_COMMIT();
        }
        const float* vv = buf[bidx];
        if (++bidx == 3) bidx = 0;

        float* a0p = attn_out + ((size_t)b * SEQ + qr) * SEQ + t * KT;
        float* a1p = a0p + (size_t)8 * SEQ;

#pragma unroll 2
        for (int nb = 0; nb < NB; nb++) {
            // read back this thread's own unnormalized E values (same addresses as k1)
            float2 e01 = *(const float2*)(a0p + nb * 8 + 2 * c);
            float2 e23 = *(const float2*)(a1p + nb * 8 + 2 * c);
            float p0 = e01.x * inv0, p1 = e01.y * inv0;
            float p2 = e23.x * inv1, p3 = e23.y * inv1;

            // store normalized attn
            *(float2*)(a0p + nb * 8 + 2 * c) = make_float2(p0, p1);
            *(float2*)(a1p + nb * 8 + 2 * c) = make_float2(p2, p3);

            // P fragments for PV (k-permutation trick: logical k c->2c, c+4->2c+1)
            uint32_t pa0 = f2t(p0), pa1 = f2t(p2), pa2 = f2t(p1), pa3 = f2t(p3);

            const int vb2 = (nb * 8 + 2 * c) * PITCH + r;
#pragma unroll
            for (int nd = 0; nd < 8; nd++) {
                // RN-round V fragments
                uint32_t b0 = f2t(vv[vb2 + 8 * nd]);
                uint32_t b1 = f2t(vv[vb2 + PITCH + 8 * nd]);
                mma8(cx[4*nd], cx[4*nd+1], cx[4*nd+2], cx[4*nd+3], pa0, pa1, pa2, pa3, b0, b1);
            }
        }
        __syncthreads();
    }

    // ---- write context ----
    float* c0p = ctx_out + ((size_t)b * SEQ + qr) * DIMD;
    float* c1p = c0p + 8 * DIMD;
#pragma unroll
    for (int nd = 0; nd < 8; nd++) {
        *(float2*)(c0p + 8 * nd + 2 * c) = make_float2(cx[4*nd],   cx[4*nd+1]);
        *(float2*)(c1p + 8 * nd + 2 * c) = make_float2(cx[4*nd+2], cx[4*nd+3]);
    }
}

// ============================ launch ============================
extern "C" void kernel_launch(void* const* d_in, const int* in_sizes, int n_in,
                              void* d_out, int out_size) {
    const float* q = (const float*)d_in[0];
    const float* k = (const float*)d_in[1];
    const float* v = (const float*)d_in[2];
    float* out = (float*)d_out;

    const long long CTX_ELEMS = (long long)BATCH * SEQ * DIMD;   // 2,097,152
    float* ctx_out  = out;
    float* attn_out = out + CTX_ELEMS;   // also used as E scratch between kernels

    cudaFuncSetAttribute(score_kernel, cudaFuncAttributeMaxDynamicSharedMemorySize, K1_SMEM);
    cudaFuncSetAttribute(pv_kernel,    cudaFuncAttributeMaxDynamicSharedMemorySize, K2_SMEM);

    score_kernel<<<BATCH * (SEQ / QT), 256, K1_SMEM>>>(q, k, attn_out);
    pv_kernel<<<BATCH * (SEQ / QT), 256, K2_SMEM>>>(v, ctx_out, attn_out);
}

// round 9
// speedup vs baseline: 1.1540x; 1.1540x over previous
#include <cuda_runtime.h>
#include <cstdint>
#include <cstddef>

// ============================ problem constants ============================
#define BATCH 16
#define SEQ   2048
#define DIMD  64
#define QT    128          // q rows per CTA
#define KT    64           // kv rows per tile
#define NKT   (SEQ / KT)   // 32
#define NB    (KT / 8)     // 8 n-blocks per tile
#define PITCH 68           // smem row pitch in floats (bank-conflict-free)
#define TILEF (KT * PITCH)         // floats per tile buffer (4352)
#define TILEB (TILEF * 4)          // bytes per tile buffer (17408)

#define RS_SMEM  (3 * TILEB)       // rowsum kernel: 3-deep K ring (52,224 B -> 4 CTAs/SM)
#define MAIN_SMEM (6 * TILEB)      // attn kernel: K[3] + V[3]     (104,448 B -> 2 CTAs/SM)

// ============================ device scratch ============================
__device__ float g_inv[(size_t)BATCH * SEQ];   // 1/rowsum per (b, q-row)

// ============================ helpers ============================
__device__ __forceinline__ uint32_t f2t(float f) {
    uint32_t u;
    asm("cvt.rna.tf32.f32 %0, %1;" : "=r"(u) : "f"(f));
    return u;
}
__device__ __forceinline__ uint32_t smem_u32(const void* p) {
    uint32_t a;
    asm("{ .reg .u64 t; cvta.to.shared.u64 t, %1; cvt.u32.u64 %0, t; }" : "=r"(a) : "l"(p));
    return a;
}
__device__ __forceinline__ void cpasync16(uint32_t dst, const float* src) {
    asm volatile("cp.async.cg.shared.global [%0], [%1], 16;" :: "r"(dst), "l"(src));
}
#define CP_COMMIT() asm volatile("cp.async.commit_group;" ::: "memory")
#define CP_WAIT(n)  asm volatile("cp.async.wait_group %0;" :: "n"(n) : "memory")

__device__ __forceinline__ void mma8(float& c0, float& c1, float& c2, float& c3,
                                     uint32_t a0, uint32_t a1, uint32_t a2, uint32_t a3,
                                     uint32_t b0, uint32_t b1) {
    asm volatile(
        "mma.sync.aligned.m16n8k8.row.col.f32.tf32.tf32.f32 "
        "{%0,%1,%2,%3},{%4,%5,%6,%7},{%8,%9},{%0,%1,%2,%3};"
        : "+f"(c0), "+f"(c1), "+f"(c2), "+f"(c3)
        : "r"(a0), "r"(a1), "r"(a2), "r"(a3), "r"(b0), "r"(b1));
}

// stage one 64x64 f32 tile (raw bits) into smem at pitch 272B via cp.async
__device__ __forceinline__ void ld_tile(uint32_t dst, const float* __restrict__ g, int tid) {
#pragma unroll
    for (int i = 0; i < 4; i++) {
        int idx = tid + i * 256;           // 1024 16B-chunks: 64 rows x 16
        int row = idx >> 4, c4 = idx & 15;
        cpasync16(dst + row * (PITCH * 4) + c4 * 16, g + row * DIMD + c4 * 4);
    }
}

// in-place RN tf32 conversion of the chunks THIS thread cp.async'd
// (only called after CP_WAIT guarantees the group arrived; visibility of own copies is implicit)
__device__ __forceinline__ void cvt_tile(float* bufp, int tid) {
#pragma unroll
    for (int i = 0; i < 4; i++) {
        int idx = tid + i * 256;
        int row = idx >> 4, c4 = idx & 15;
        float4* p = (float4*)&bufp[row * PITCH + c4 * 4];
        float4 v = *p;
        v.x = __uint_as_float(f2t(v.x));
        v.y = __uint_as_float(f2t(v.y));
        v.z = __uint_as_float(f2t(v.z));
        v.w = __uint_as_float(f2t(v.w));
        *p = v;
    }
}

// load this lane's Q fragments (single tf32, RN, pre-scaled by 1/8)
__device__ __forceinline__ void load_q_frags(uint32_t* qh, const float* __restrict__ Q,
                                             int b, int qr, int c) {
    const float* q0p = Q + ((size_t)b * SEQ + qr) * DIMD;
    const float* q1p = q0p + 8 * DIMD;
#pragma unroll
    for (int j = 0; j < 8; j++) {
        qh[4*j+0] = f2t(q0p[8 * j + c]     * 0.125f);
        qh[4*j+1] = f2t(q1p[8 * j + c]     * 0.125f);
        qh[4*j+2] = f2t(q0p[8 * j + c + 4] * 0.125f);
        qh[4*j+3] = f2t(q1p[8 * j + c + 4] * 0.125f);
    }
}

// ============================ kernel 1: rowsums (high occupancy) ============================
__global__ void __launch_bounds__(256, 4)
rowsum_kernel(const float* __restrict__ Q, const float* __restrict__ K)
{
    extern __shared__ float sm[];
    float* buf[3] = { sm, sm + TILEF, sm + 2 * TILEF };
    const uint32_t smb = smem_u32(sm);
    const uint32_t bd[3] = { smb, smb + TILEB, smb + 2 * TILEB };

    const int tid  = threadIdx.x;
    const int w    = tid >> 5;
    const int lane = tid & 31;
    const int r    = lane >> 2;
    const int c    = lane & 3;

    const int b  = blockIdx.x >> 4;
    const int q0 = (blockIdx.x & 15) << 7;
    const int qr = q0 + 16 * w + r;

    const float* Kb = K + (size_t)b * SEQ * DIMD;

    uint32_t qh[32];
    load_q_frags(qh, Q, b, qr, c);

    float rs0 = 0.f, rs1 = 0.f;
    ld_tile(bd[0], Kb, tid); CP_COMMIT();
    ld_tile(bd[1], Kb + (size_t)KT * DIMD, tid); CP_COMMIT();
    int bidx = 0;
    for (int t = 0; t < NKT; t++) {
        CP_WAIT(1);
        __syncthreads();
        if (t + 2 < NKT) {
            int nb2 = bidx + 2; if (nb2 >= 3) nb2 -= 3;
            ld_tile(bd[nb2], Kb + (size_t)(t + 2) * KT * DIMD, tid);
            CP_COMMIT();
        }
        const float* kh = buf[bidx];
        if (++bidx == 3) bidx = 0;
#pragma unroll
        for (int nb = 0; nb < NB; nb++) {
            float e0 = 0.f, e1 = 0.f, e2 = 0.f, e3 = 0.f;
            float o0 = 0.f, o1 = 0.f, o2 = 0.f, o3 = 0.f;
            const int base = (nb * 8 + r) * PITCH + c;
#pragma unroll
            for (int j2 = 0; j2 < 4; j2++) {
                const int je = 2 * j2, jo = 2 * j2 + 1;
                uint32_t be0 = __float_as_uint(kh[base + 8 * je]);
                uint32_t be1 = __float_as_uint(kh[base + 8 * je + 4]);
                uint32_t bo0 = __float_as_uint(kh[base + 8 * jo]);
                uint32_t bo1 = __float_as_uint(kh[base + 8 * jo + 4]);
                mma8(e0, e1, e2, e3, qh[4*je], qh[4*je+1], qh[4*je+2], qh[4*je+3], be0, be1);
                mma8(o0, o1, o2, o3, qh[4*jo], qh[4*jo+1], qh[4*jo+2], qh[4*jo+3], bo0, bo1);
            }
            rs0 += __expf(e0 + o0) + __expf(e1 + o1);
            rs1 += __expf(e2 + o2) + __expf(e3 + o3);
        }
        __syncthreads();
    }
    rs0 += __shfl_xor_sync(0xFFFFFFFFu, rs0, 1);
    rs0 += __shfl_xor_sync(0xFFFFFFFFu, rs0, 2);
    rs1 += __shfl_xor_sync(0xFFFFFFFFu, rs1, 1);
    rs1 += __shfl_xor_sync(0xFFFFFFFFu, rs1, 2);
    if (c == 0) {
        g_inv[(size_t)b * SEQ + qr]     = 1.0f / rs0;
        g_inv[(size_t)b * SEQ + qr + 8] = 1.0f / rs1;
    }
}

// ============================ kernel 2: attn + context ============================
// 3-deep K/V rings; tile t+1 is RN-converted in place at the END of step t,
// after it has had a full compute step to arrive (stall-free cvt hoist).
__global__ void __launch_bounds__(256, 2)
attn_kernel(const float* __restrict__ Q, const float* __restrict__ K,
            const float* __restrict__ V, float* __restrict__ ctx_out,
            float* __restrict__ attn_out, int has_attn)
{
    extern __shared__ float sm[];
    float* kbuf[3] = { sm,             sm + TILEF,     sm + 2 * TILEF };
    float* vbuf[3] = { sm + 3 * TILEF, sm + 4 * TILEF, sm + 5 * TILEF };
    const uint32_t smb = smem_u32(sm);
    const uint32_t kd[3] = { smb,             smb + TILEB,     smb + 2 * TILEB };
    const uint32_t vd[3] = { smb + 3 * TILEB, smb + 4 * TILEB, smb + 5 * TILEB };

    const int tid  = threadIdx.x;
    const int w    = tid >> 5;
    const int lane = tid & 31;
    const int r    = lane >> 2;
    const int c    = lane & 3;

    const int b  = blockIdx.x >> 4;
    const int q0 = (blockIdx.x & 15) << 7;
    const int qr = q0 + 16 * w + r;

    const float* Kb = K + (size_t)b * SEQ * DIMD;
    const float* Vb = V + (size_t)b * SEQ * DIMD;

    // prologue: stage tiles 0 and 1 (each group = K tile + V tile)
    ld_tile(kd[0], Kb, tid);
    ld_tile(vd[0], Vb, tid);
    CP_COMMIT();
    ld_tile(kd[1], Kb + (size_t)KT * DIMD, tid);
    ld_tile(vd[1], Vb + (size_t)KT * DIMD, tid);
    CP_COMMIT();

    uint32_t qh[32];
    load_q_frags(qh, Q, b, qr, c);

    const float inv0 = g_inv[(size_t)b * SEQ + qr];
    const float inv1 = g_inv[(size_t)b * SEQ + qr + 8];

    float cx[32];
#pragma unroll
    for (int i = 0; i < 32; i++) cx[i] = 0.f;

    // convert tile 0 (own chunks) before the mainloop
    CP_WAIT(1);
    cvt_tile(kbuf[0], tid);
    cvt_tile(vbuf[0], tid);
    __syncthreads();

    int cur = 0;   // buffer index of tile t
    for (int t = 0; t < NKT; t++) {
        // prefetch tile t+2 into buffer (cur+2)%3 (that tile finished compute at step t-1)
        if (t + 2 < NKT) {
            int nxt2 = cur + 2; if (nxt2 >= 3) nxt2 -= 3;
            ld_tile(kd[nxt2], Kb + (size_t)(t + 2) * KT * DIMD, tid);
            ld_tile(vd[nxt2], Vb + (size_t)(t + 2) * KT * DIMD, tid);
            CP_COMMIT();
        }

        const float* kh = kbuf[cur];
        const float* vv = vbuf[cur];

        float* a0p = attn_out + ((size_t)b * SEQ + qr) * SEQ + t * KT;
        float* a1p = a0p + (size_t)8 * SEQ;

#pragma unroll 2
        for (int nb = 0; nb < NB; nb++) {
            float e0 = 0.f, e1 = 0.f, e2 = 0.f, e3 = 0.f;
            float o0 = 0.f, o1 = 0.f, o2 = 0.f, o3 = 0.f;
            const int base = (nb * 8 + r) * PITCH + c;
#pragma unroll
            for (int j2 = 0; j2 < 4; j2++) {
                const int je = 2 * j2, jo = 2 * j2 + 1;
                uint32_t be0 = __float_as_uint(kh[base + 8 * je]);
                uint32_t be1 = __float_as_uint(kh[base + 8 * je + 4]);
                uint32_t bo0 = __float_as_uint(kh[base + 8 * jo]);
                uint32_t bo1 = __float_as_uint(kh[base + 8 * jo + 4]);
                mma8(e0, e1, e2, e3, qh[4*je], qh[4*je+1], qh[4*je+2], qh[4*je+3], be0, be1);
                mma8(o0, o1, o2, o3, qh[4*jo], qh[4*jo+1], qh[4*jo+2], qh[4*jo+3], bo0, bo1);
            }
            float p0 = __expf(e0 + o0) * inv0;
            float p1 = __expf(e1 + o1) * inv0;
            float p2 = __expf(e2 + o2) * inv1;
            float p3 = __expf(e3 + o3) * inv1;

            if (has_attn) {
                *(float2*)(a0p + nb * 8 + 2 * c) = make_float2(p0, p1);
                *(float2*)(a1p + nb * 8 + 2 * c) = make_float2(p2, p3);
            }

            // P fragments for PV (k-permutation trick: logical k c->2c, c+4->2c+1)
            uint32_t pa0 = f2t(p0), pa1 = f2t(p2), pa2 = f2t(p1), pa3 = f2t(p3);

            const int vb2 = (nb * 8 + 2 * c) * PITCH + r;
#pragma unroll
            for (int nd = 0; nd < 8; nd++) {
                uint32_t b0 = __float_as_uint(vv[vb2 + 8 * nd]);
                uint32_t b1 = __float_as_uint(vv[vb2 + PITCH + 8 * nd]);
                mma8(cx[4*nd], cx[4*nd+1], cx[4*nd+2], cx[4*nd+3], pa0, pa1, pa2, pa3, b0, b1);
            }
        }

        // end-of-step: ensure tile t+1 has arrived, convert it in place (own chunks)
        if (t + 1 < NKT) {
            int nxt = cur + 1; if (nxt >= 3) nxt -= 3;
            if (t + 2 < NKT) { CP_WAIT(1); }   // newest (t+2) may stay pending
            else            { CP_WAIT(0); }   // nothing newer committed: force t+1
            cvt_tile(kbuf[nxt], tid);
            cvt_tile(vbuf[nxt], tid);
        }
        __syncthreads();   // cvt'd tile + buffer reuse visible to all warps

        if (++cur == 3) cur = 0;
    }

    // ---- write context ----
    float* c0p = ctx_out + ((size_t)b * SEQ + qr) * DIMD;
    float* c1p = c0p + 8 * DIMD;
#pragma unroll
    for (int nd = 0; nd < 8; nd++) {
        *(float2*)(c0p + 8 * nd + 2 * c) = make_float2(cx[4*nd],   cx[4*nd+1]);
        *(float2*)(c1p + 8 * nd + 2 * c) = make_float2(cx[4*nd+2], cx[4*nd+3]);
    }
}

// ============================ launch ============================
extern "C" void kernel_launch(void* const* d_in, const int* in_sizes, int n_in,
                              void* d_out, int out_size) {
    const float* q = (const float*)d_in[0];
    const float* k = (const float*)d_in[1];
    const float* v = (const float*)d_in[2];
    float* out = (float*)d_out;

    const long long CTX_ELEMS  = (long long)BATCH * SEQ * DIMD;   // 2,097,152
    const long long ATTN_ELEMS = (long long)BATCH * SEQ * SEQ;    // 67,108,864
    float* ctx_out  = out;
    float* attn_out = out + CTX_ELEMS;
    int has_attn = ((long long)out_size >= CTX_ELEMS + ATTN_ELEMS) ? 1 : 0;

    cudaFuncSetAttribute(rowsum_kernel, cudaFuncAttributeMaxDynamicSharedMemorySize, RS_SMEM);
    cudaFuncSetAttribute(attn_kernel,   cudaFuncAttributeMaxDynamicSharedMemorySize, MAIN_SMEM);

    rowsum_kernel<<<BATCH * (SEQ / QT), 256, RS_SMEM>>>(q, k);
    attn_kernel<<<BATCH * (SEQ / QT), 256, MAIN_SMEM>>>(q, k, v, ctx_out, attn_out, has_attn);
}

// round 10
// speedup vs baseline: 1.3937x; 1.2077x over previous
#include <cuda_runtime.h>
#include <cstdint>
#include <cstddef>

// ============================ problem constants ============================
#define BATCH 16
#define SEQ   2048
#define DIMD  64
#define QT    128          // q rows per CTA
#define KT    64           // kv rows per tile
#define NKT   (SEQ / KT)   // 32
#define NB    (KT / 8)     // 8 n-blocks per tile
#define KPITCH 72          // K smem pitch (floats): LDS.64 phase-conflict-free
#define VPITCH 68          // V smem pitch (floats): LDS.32 conflict-free
#define KTILEF (KT * KPITCH)       // 4608 floats
#define KTILEB (KTILEF * 4)        // 18432 B
#define VTILEF (KT * VPITCH)       // 4352 floats
#define VTILEB (VTILEF * 4)        // 17408 B

#define RS_SMEM   (3 * KTILEB)             // 55,296 B  -> 4 CTAs/SM
#define MAIN_SMEM (3 * KTILEB + 3 * VTILEB) // 107,520 B -> 2 CTAs/SM

#define NELEM  ((size_t)BATCH * SEQ * DIMD)   // 2,097,152

// ============================ device scratch ============================
__device__ float g_inv[(size_t)BATCH * SEQ];  // 1/rowsum per (b, q-row)
__device__ float g_kr[NELEM];                 // K pre-rounded to tf32 (RN)
__device__ float g_vr[NELEM];                 // V pre-rounded to tf32 (RN)

// ============================ helpers ============================
__device__ __forceinline__ uint32_t f2t(float f) {
    uint32_t u;
    asm("cvt.rna.tf32.f32 %0, %1;" : "=r"(u) : "f"(f));
    return u;
}
__device__ __forceinline__ uint32_t smem_u32(const void* p) {
    uint32_t a;
    asm("{ .reg .u64 t; cvta.to.shared.u64 t, %1; cvt.u32.u64 %0, t; }" : "=r"(a) : "l"(p));
    return a;
}
__device__ __forceinline__ void cpasync16(uint32_t dst, const float* src) {
    asm volatile("cp.async.cg.shared.global [%0], [%1], 16;" :: "r"(dst), "l"(src));
}
#define CP_COMMIT() asm volatile("cp.async.commit_group;" ::: "memory")
#define CP_WAIT(n)  asm volatile("cp.async.wait_group %0;" :: "n"(n) : "memory")

__device__ __forceinline__ void mma8(float& c0, float& c1, float& c2, float& c3,
                                     uint32_t a0, uint32_t a1, uint32_t a2, uint32_t a3,
                                     uint32_t b0, uint32_t b1) {
    asm volatile(
        "mma.sync.aligned.m16n8k8.row.col.f32.tf32.tf32.f32 "
        "{%0,%1,%2,%3},{%4,%5,%6,%7},{%8,%9},{%0,%1,%2,%3};"
        : "+f"(c0), "+f"(c1), "+f"(c2), "+f"(c3)
        : "r"(a0), "r"(a1), "r"(a2), "r"(a3), "r"(b0), "r"(b1));
}

// stage one 64x64 f32 tile into smem (pitchB bytes per row) via cp.async
__device__ __forceinline__ void ld_tile(uint32_t dst, const float* __restrict__ g,
                                        int tid, int pitchB) {
#pragma unroll
    for (int i = 0; i < 4; i++) {
        int idx = tid + i * 256;           // 1024 16B-chunks: 64 rows x 16
        int row = idx >> 4, c4 = idx & 15;
        cpasync16(dst + row * pitchB + c4 * 16, g + row * DIMD + c4 * 4);
    }
}

// Q fragments under the QK k-permutation sigma(c)=2c, sigma(c+4)=2c+1 (per 8-chunk):
// a0 = Q[qr][8j+2c], a1 = Q[qr+8][8j+2c], a2 = Q[qr][8j+2c+1], a3 = Q[qr+8][8j+2c+1]
__device__ __forceinline__ void load_q_frags(uint32_t* qh, const float* __restrict__ Q,
                                             int b, int qr, int c) {
    const float* q0p = Q + ((size_t)b * SEQ + qr) * DIMD;
    const float* q1p = q0p + 8 * DIMD;
#pragma unroll
    for (int j = 0; j < 8; j++) {
        qh[4*j+0] = f2t(q0p[8 * j + 2 * c]     * 0.125f);
        qh[4*j+1] = f2t(q1p[8 * j + 2 * c]     * 0.125f);
        qh[4*j+2] = f2t(q0p[8 * j + 2 * c + 1] * 0.125f);
        qh[4*j+3] = f2t(q1p[8 * j + 2 * c + 1] * 0.125f);
    }
}

// QK inner loop: 8 LDS.64 + 8 mma (K already tf32-rounded in smem)
__device__ __forceinline__ void qk_block(float& e0, float& e1, float& e2, float& e3,
                                         float& o0, float& o1, float& o2, float& o3,
                                         const float* kh, const uint32_t* qh,
                                         int nb, int r, int c) {
    const int kbase = (nb * 8 + r) * KPITCH + 2 * c;
#pragma unroll
    for (int j2 = 0; j2 < 4; j2++) {
        const int je = 2 * j2, jo = 2 * j2 + 1;
        float2 ke = *(const float2*)&kh[kbase + 8 * je];
        float2 ko = *(const float2*)&kh[kbase + 8 * jo];
        mma8(e0, e1, e2, e3, qh[4*je], qh[4*je+1], qh[4*je+2], qh[4*je+3],
             __float_as_uint(ke.x), __float_as_uint(ke.y));
        mma8(o0, o1, o2, o3, qh[4*jo], qh[4*jo+1], qh[4*jo+2], qh[4*jo+3],
             __float_as_uint(ko.x), __float_as_uint(ko.y));
    }
}

// ============================ kernel 0: pre-round K and V to tf32 ============================
__global__ void __launch_bounds__(256)
preround_kernel(const float* __restrict__ K, const float* __restrict__ V) {
    size_t i = (size_t)blockIdx.x * blockDim.x + threadIdx.x;   // one float4 per thread
    const size_t N4 = NELEM / 4;
    if (i < N4) {
        float4 a = ((const float4*)K)[i];
        a.x = __uint_as_float(f2t(a.x)); a.y = __uint_as_float(f2t(a.y));
        a.z = __uint_as_float(f2t(a.z)); a.w = __uint_as_float(f2t(a.w));
        ((float4*)g_kr)[i] = a;
        float4 b = ((const float4*)V)[i];
        b.x = __uint_as_float(f2t(b.x)); b.y = __uint_as_float(f2t(b.y));
        b.z = __uint_as_float(f2t(b.z)); b.w = __uint_as_float(f2t(b.w));
        ((float4*)g_vr)[i] = b;
    }
}

// ============================ kernel 1: rowsums (high occupancy) ============================
__global__ void __launch_bounds__(256, 4)
rowsum_kernel(const float* __restrict__ Q)
{
    extern __shared__ float sm[];
    float* buf[3] = { sm, sm + KTILEF, sm + 2 * KTILEF };
    const uint32_t smb = smem_u32(sm);
    const uint32_t bd[3] = { smb, smb + KTILEB, smb + 2 * KTILEB };

    const int tid  = threadIdx.x;
    const int w    = tid >> 5;
    const int lane = tid & 31;
    const int r    = lane >> 2;
    const int c    = lane & 3;

    const int b  = blockIdx.x >> 4;
    const int q0 = (blockIdx.x & 15) << 7;
    const int qr = q0 + 16 * w + r;

    const float* Kb = g_kr + (size_t)b * SEQ * DIMD;

    uint32_t qh[32];
    load_q_frags(qh, Q, b, qr, c);

    float rs0 = 0.f, rs1 = 0.f;
    ld_tile(bd[0], Kb, tid, KPITCH * 4); CP_COMMIT();
    ld_tile(bd[1], Kb + (size_t)KT * DIMD, tid, KPITCH * 4); CP_COMMIT();
    int bidx = 0;
    for (int t = 0; t < NKT; t++) {
        CP_WAIT(1);
        __syncthreads();
        if (t + 2 < NKT) {
            int nb2 = bidx + 2; if (nb2 >= 3) nb2 -= 3;
            ld_tile(bd[nb2], Kb + (size_t)(t + 2) * KT * DIMD, tid, KPITCH * 4);
            CP_COMMIT();
        }
        const float* kh = buf[bidx];
        if (++bidx == 3) bidx = 0;
#pragma unroll
        for (int nb = 0; nb < NB; nb++) {
            float e0 = 0.f, e1 = 0.f, e2 = 0.f, e3 = 0.f;
            float o0 = 0.f, o1 = 0.f, o2 = 0.f, o3 = 0.f;
            qk_block(e0, e1, e2, e3, o0, o1, o2, o3, kh, qh, nb, r, c);
            rs0 += __expf(e0 + o0) + __expf(e1 + o1);
            rs1 += __expf(e2 + o2) + __expf(e3 + o3);
        }
        __syncthreads();
    }
    rs0 += __shfl_xor_sync(0xFFFFFFFFu, rs0, 1);
    rs0 += __shfl_xor_sync(0xFFFFFFFFu, rs0, 2);
    rs1 += __shfl_xor_sync(0xFFFFFFFFu, rs1, 1);
    rs1 += __shfl_xor_sync(0xFFFFFFFFu, rs1, 2);
    if (c == 0) {
        g_inv[(size_t)b * SEQ + qr]     = 1.0f / rs0;
        g_inv[(size_t)b * SEQ + qr + 8] = 1.0f / rs1;
    }
}

// ============================ kernel 2: attn + context ============================
__global__ void __launch_bounds__(256, 2)
attn_kernel(const float* __restrict__ Q, float* __restrict__ ctx_out,
            float* __restrict__ attn_out, int has_attn)
{
    extern __shared__ float sm[];
    float* kbuf[3] = { sm, sm + KTILEF, sm + 2 * KTILEF };
    float* vbuf[3] = { sm + 3 * KTILEF, sm + 3 * KTILEF + VTILEF, sm + 3 * KTILEF + 2 * VTILEF };
    const uint32_t smb = smem_u32(sm);
    const uint32_t kd[3] = { smb, smb + KTILEB, smb + 2 * KTILEB };
    const uint32_t vd[3] = { smb + 3 * KTILEB, smb + 3 * KTILEB + VTILEB, smb + 3 * KTILEB + 2 * VTILEB };

    const int tid  = threadIdx.x;
    const int w    = tid >> 5;
    const int lane = tid & 31;
    const int r    = lane >> 2;
    const int c    = lane & 3;

    const int b  = blockIdx.x >> 4;
    const int q0 = (blockIdx.x & 15) << 7;
    const int qr = q0 + 16 * w + r;

    const float* Kb = g_kr + (size_t)b * SEQ * DIMD;
    const float* Vb = g_vr + (size_t)b * SEQ * DIMD;

    // prologue: stage tiles 0 and 1 (each group = K tile + V tile)
    ld_tile(kd[0], Kb, tid, KPITCH * 4);
    ld_tile(vd[0], Vb, tid, VPITCH * 4);
    CP_COMMIT();
    ld_tile(kd[1], Kb + (size_t)KT * DIMD, tid, KPITCH * 4);
    ld_tile(vd[1], Vb + (size_t)KT * DIMD, tid, VPITCH * 4);
    CP_COMMIT();

    uint32_t qh[32];
    load_q_frags(qh, Q, b, qr, c);

    const float inv0 = g_inv[(size_t)b * SEQ + qr];
    const float inv1 = g_inv[(size_t)b * SEQ + qr + 8];

    float cx[32];
#pragma unroll
    for (int i = 0; i < 32; i++) cx[i] = 0.f;

    int bidx = 0;
    for (int t = 0; t < NKT; t++) {
        CP_WAIT(1);
        __syncthreads();
        if (t + 2 < NKT) {
            int nb2 = bidx + 2; if (nb2 >= 3) nb2 -= 3;
            ld_tile(kd[nb2], Kb + (size_t)(t + 2) * KT * DIMD, tid, KPITCH * 4);
            ld_tile(vd[nb2], Vb + (size_t)(t + 2) * KT * DIMD, tid, VPITCH * 4);
            CP_COMMIT();
        }
        const float* kh = kbuf[bidx];
        const float* vv = vbuf[bidx];
        if (++bidx == 3) bidx = 0;

        float* a0p = attn_out + ((size_t)b * SEQ + qr) * SEQ + t * KT;
        float* a1p = a0p + (size_t)8 * SEQ;

#pragma unroll 2
        for (int nb = 0; nb < NB; nb++) {
            float e0 = 0.f, e1 = 0.f, e2 = 0.f, e3 = 0.f;
            float o0 = 0.f, o1 = 0.f, o2 = 0.f, o3 = 0.f;
            qk_block(e0, e1, e2, e3, o0, o1, o2, o3, kh, qh, nb, r, c);

            float p0 = __expf(e0 + o0) * inv0;
            float p1 = __expf(e1 + o1) * inv0;
            float p2 = __expf(e2 + o2) * inv1;
            float p3 = __expf(e3 + o3) * inv1;

            if (has_attn) {
                *(float2*)(a0p + nb * 8 + 2 * c) = make_float2(p0, p1);
                *(float2*)(a1p + nb * 8 + 2 * c) = make_float2(p2, p3);
            }

            // P fragments for PV (k-permutation trick: logical k c->2c, c+4->2c+1)
            uint32_t pa0 = f2t(p0), pa1 = f2t(p2), pa2 = f2t(p1), pa3 = f2t(p3);

            const int vb2 = (nb * 8 + 2 * c) * VPITCH + r;
#pragma unroll
            for (int nd = 0; nd < 8; nd++) {
                uint32_t b0 = __float_as_uint(vv[vb2 + 8 * nd]);
                uint32_t b1 = __float_as_uint(vv[vb2 + VPITCH + 8 * nd]);
                mma8(cx[4*nd], cx[4*nd+1], cx[4*nd+2], cx[4*nd+3], pa0, pa1, pa2, pa3, b0, b1);
            }
        }
        __syncthreads();
    }

    // ---- write context ----
    float* c0p = ctx_out + ((size_t)b * SEQ + qr) * DIMD;
    float* c1p = c0p + 8 * DIMD;
#pragma unroll
    for (int nd = 0; nd < 8; nd++) {
        *(float2*)(c0p + 8 * nd + 2 * c) = make_float2(cx[4*nd],   cx[4*nd+1]);
        *(float2*)(c1p + 8 * nd + 2 * c) = make_float2(cx[4*nd+2], cx[4*nd+3]);
    }
}

// ============================ launch ============================
extern "C" void kernel_launch(void* const* d_in, const int* in_sizes, int n_in,
                              void* d_out, int out_size) {
    const float* q = (const float*)d_in[0];
    const float* k = (const float*)d_in[1];
    const float* v = (const float*)d_in[2];
    float* out = (float*)d_out;

    const long long CTX_ELEMS  = (long long)BATCH * SEQ * DIMD;   // 2,097,152
    const long long ATTN_ELEMS = (long long)BATCH * SEQ * SEQ;    // 67,108,864
    float* ctx_out  = out;
    float* attn_out = out + CTX_ELEMS;
    int has_attn = ((long long)out_size >= CTX_ELEMS + ATTN_ELEMS) ? 1 : 0;

    cudaFuncSetAttribute(rowsum_kernel, cudaFuncAttributeMaxDynamicSharedMemorySize, RS_SMEM);
    cudaFuncSetAttribute(attn_kernel,   cudaFuncAttributeMaxDynamicSharedMemorySize, MAIN_SMEM);

    preround_kernel<<<(unsigned)(NELEM / 4 / 256), 256>>>(k, v);
    rowsum_kernel<<<BATCH * (SEQ / QT), 256, RS_SMEM>>>(q);
    attn_kernel<<<BATCH * (SEQ / QT), 256, MAIN_SMEM>>>(q, ctx_out, attn_out, has_attn);
}

// round 11
// speedup vs baseline: 1.4606x; 1.0480x over previous
#include <cuda_runtime.h>
#include <cstdint>
#include <cstddef>

// ============================ problem constants ============================
#define BATCH 16
#define SEQ   2048
#define DIMD  64
#define QT    128          // q rows per CTA
#define KT    64           // kv rows per tile
#define NKT   (SEQ / KT)   // 32
#define NB    (KT / 8)     // 8 n-blocks per tile
#define KPITCH 72          // K smem pitch (floats): LDS.64 phase-conflict-free
#define VPITCH 72          // V^T smem pitch (floats): LDS.64 phase-conflict-free
#define KTILEF (KT * KPITCH)       // 4608 floats
#define KTILEB (KTILEF * 4)        // 18432 B
#define VTILEF (DIMD * VPITCH)     // 4608 floats (64 d-rows x 72)
#define VTILEB (VTILEF * 4)        // 18432 B

#define RS_SMEM   (3 * KTILEB)              // 55,296 B  -> 4 CTAs/SM
#define MAIN_SMEM (3 * KTILEB + 3 * VTILEB) // 110,592 B -> 2 CTAs/SM

#define NELEM  ((size_t)BATCH * SEQ * DIMD)   // 2,097,152

// ============================ device scratch ============================
__device__ float g_inv[(size_t)BATCH * SEQ];  // 1/rowsum per (b, q-row)
__device__ float g_kr[NELEM];                 // K pre-rounded to tf32 (RN), [b][s][d]
__device__ float g_vt[NELEM];                 // V^T pre-rounded to tf32 (RN), [b][d][s]

// ============================ helpers ============================
__device__ __forceinline__ uint32_t f2t(float f) {
    uint32_t u;
    asm("cvt.rna.tf32.f32 %0, %1;" : "=r"(u) : "f"(f));
    return u;
}
__device__ __forceinline__ uint32_t smem_u32(const void* p) {
    uint32_t a;
    asm("{ .reg .u64 t; cvta.to.shared.u64 t, %1; cvt.u32.u64 %0, t; }" : "=r"(a) : "l"(p));
    return a;
}
__device__ __forceinline__ void cpasync16(uint32_t dst, const float* src) {
    asm volatile("cp.async.cg.shared.global [%0], [%1], 16;" :: "r"(dst), "l"(src));
}
#define CP_COMMIT() asm volatile("cp.async.commit_group;" ::: "memory")
#define CP_WAIT(n)  asm volatile("cp.async.wait_group %0;" :: "n"(n) : "memory")

__device__ __forceinline__ void mma8(float& c0, float& c1, float& c2, float& c3,
                                     uint32_t a0, uint32_t a1, uint32_t a2, uint32_t a3,
                                     uint32_t b0, uint32_t b1) {
    asm volatile(
        "mma.sync.aligned.m16n8k8.row.col.f32.tf32.tf32.f32 "
        "{%0,%1,%2,%3},{%4,%5,%6,%7},{%8,%9},{%0,%1,%2,%3};"
        : "+f"(c0), "+f"(c1), "+f"(c2), "+f"(c3)
        : "r"(a0), "r"(a1), "r"(a2), "r"(a3), "r"(b0), "r"(b1));
}

// stage one 64-row x 64-float tile into smem via cp.async
// gstride = gmem row stride in floats, pitchB = smem row pitch in bytes
__device__ __forceinline__ void ld_tile(uint32_t dst, const float* __restrict__ g,
                                        int tid, int gstride, int pitchB) {
#pragma unroll
    for (int i = 0; i < 4; i++) {
        int idx = tid + i * 256;           // 1024 16B-chunks: 64 rows x 16
        int row = idx >> 4, c4 = idx & 15;
        cpasync16(dst + row * pitchB + c4 * 16, g + (size_t)row * gstride + c4 * 4);
    }
}

// Q fragments under the QK k-permutation sigma(c)=2c, sigma(c+4)=2c+1 (per 8-chunk)
__device__ __forceinline__ void load_q_frags(uint32_t* qh, const float* __restrict__ Q,
                                             int b, int qr, int c) {
    const float* q0p = Q + ((size_t)b * SEQ + qr) * DIMD;
    const float* q1p = q0p + 8 * DIMD;
#pragma unroll
    for (int j = 0; j < 8; j++) {
        qh[4*j+0] = f2t(q0p[8 * j + 2 * c]     * 0.125f);
        qh[4*j+1] = f2t(q1p[8 * j + 2 * c]     * 0.125f);
        qh[4*j+2] = f2t(q0p[8 * j + 2 * c + 1] * 0.125f);
        qh[4*j+3] = f2t(q1p[8 * j + 2 * c + 1] * 0.125f);
    }
}

// QK inner loop: 8 LDS.64 + 8 mma (K already tf32-rounded in smem)
__device__ __forceinline__ void qk_block(float& e0, float& e1, float& e2, float& e3,
                                         float& o0, float& o1, float& o2, float& o3,
                                         const float* kh, const uint32_t* qh,
                                         int nb, int r, int c) {
    const int kbase = (nb * 8 + r) * KPITCH + 2 * c;
#pragma unroll
    for (int j2 = 0; j2 < 4; j2++) {
        const int je = 2 * j2, jo = 2 * j2 + 1;
        float2 ke = *(const float2*)&kh[kbase + 8 * je];
        float2 ko = *(const float2*)&kh[kbase + 8 * jo];
        mma8(e0, e1, e2, e3, qh[4*je], qh[4*je+1], qh[4*je+2], qh[4*je+3],
             __float_as_uint(ke.x), __float_as_uint(ke.y));
        mma8(o0, o1, o2, o3, qh[4*jo], qh[4*jo+1], qh[4*jo+2], qh[4*jo+3],
             __float_as_uint(ko.x), __float_as_uint(ko.y));
    }
}

// ============================ kernel 0a: pre-round K ============================
__global__ void __launch_bounds__(256)
kround_kernel(const float* __restrict__ K) {
    size_t i = (size_t)blockIdx.x * blockDim.x + threadIdx.x;
    if (i < NELEM / 4) {
        float4 a = ((const float4*)K)[i];
        a.x = __uint_as_float(f2t(a.x)); a.y = __uint_as_float(f2t(a.y));
        a.z = __uint_as_float(f2t(a.z)); a.w = __uint_as_float(f2t(a.w));
        ((float4*)g_kr)[i] = a;
    }
}

// ============================ kernel 0b: transpose + pre-round V ============================
__global__ void __launch_bounds__(256)
vtrans_kernel(const float* __restrict__ V) {
    __shared__ float tile[32][33];
    const int b = blockIdx.z, s0 = blockIdx.x * 32, d0 = blockIdx.y * 32;
    const int tx = threadIdx.x, ty = threadIdx.y;
#pragma unroll
    for (int i = 0; i < 4; i++) {
        int s = ty + i * 8;
        tile[s][tx] = V[((size_t)(b * SEQ + s0 + s)) * DIMD + d0 + tx];
    }
    __syncthreads();
#pragma unroll
    for (int i = 0; i < 4; i++) {
        int d = ty + i * 8;
        g_vt[((size_t)(b * DIMD + d0 + d)) * SEQ + s0 + tx] =
            __uint_as_float(f2t(tile[tx][d]));
    }
}

// ============================ kernel 1: rowsums (high occupancy) ============================
__global__ void __launch_bounds__(256, 4)
rowsum_kernel(const float* __restrict__ Q)
{
    extern __shared__ float sm[];
    float* buf[3] = { sm, sm + KTILEF, sm + 2 * KTILEF };
    const uint32_t smb = smem_u32(sm);
    const uint32_t bd[3] = { smb, smb + KTILEB, smb + 2 * KTILEB };

    const int tid  = threadIdx.x;
    const int w    = tid >> 5;
    const int lane = tid & 31;
    const int r    = lane >> 2;
    const int c    = lane & 3;

    const int b  = blockIdx.x >> 4;
    const int q0 = (blockIdx.x & 15) << 7;
    const int qr = q0 + 16 * w + r;

    const float* Kb = g_kr + (size_t)b * SEQ * DIMD;

    uint32_t qh[32];
    load_q_frags(qh, Q, b, qr, c);

    float rs0 = 0.f, rs1 = 0.f;
    ld_tile(bd[0], Kb, tid, DIMD, KPITCH * 4); CP_COMMIT();
    ld_tile(bd[1], Kb + (size_t)KT * DIMD, tid, DIMD, KPITCH * 4); CP_COMMIT();
    int bidx = 0;
    for (int t = 0; t < NKT; t++) {
        CP_WAIT(1);
        __syncthreads();
        if (t + 2 < NKT) {
            int nb2 = bidx + 2; if (nb2 >= 3) nb2 -= 3;
            ld_tile(bd[nb2], Kb + (size_t)(t + 2) * KT * DIMD, tid, DIMD, KPITCH * 4);
            CP_COMMIT();
        }
        const float* kh = buf[bidx];
        if (++bidx == 3) bidx = 0;
#pragma unroll
        for (int nb = 0; nb < NB; nb++) {
            float e0 = 0.f, e1 = 0.f, e2 = 0.f, e3 = 0.f;
            float o0 = 0.f, o1 = 0.f, o2 = 0.f, o3 = 0.f;
            qk_block(e0, e1, e2, e3, o0, o1, o2, o3, kh, qh, nb, r, c);
            rs0 += __expf(e0 + o0) + __expf(e1 + o1);
            rs1 += __expf(e2 + o2) + __expf(e3 + o3);
        }
        __syncthreads();
    }
    rs0 += __shfl_xor_sync(0xFFFFFFFFu, rs0, 1);
    rs0 += __shfl_xor_sync(0xFFFFFFFFu, rs0, 2);
    rs1 += __shfl_xor_sync(0xFFFFFFFFu, rs1, 1);
    rs1 += __shfl_xor_sync(0xFFFFFFFFu, rs1, 2);
    if (c == 0) {
        g_inv[(size_t)b * SEQ + qr]     = 1.0f / rs0;
        g_inv[(size_t)b * SEQ + qr + 8] = 1.0f / rs1;
    }
}

// ============================ kernel 2: attn + context ============================
__global__ void __launch_bounds__(256, 2)
attn_kernel(const float* __restrict__ Q, float* __restrict__ ctx_out,
            float* __restrict__ attn_out, int has_attn)
{
    extern __shared__ float sm[];
    float* kbuf[3] = { sm, sm + KTILEF, sm + 2 * KTILEF };
    float* vbuf[3] = { sm + 3 * KTILEF, sm + 3 * KTILEF + VTILEF, sm + 3 * KTILEF + 2 * VTILEF };
    const uint32_t smb = smem_u32(sm);
    const uint32_t kd[3] = { smb, smb + KTILEB, smb + 2 * KTILEB };
    const uint32_t vd[3] = { smb + 3 * KTILEB, smb + 3 * KTILEB + VTILEB, smb + 3 * KTILEB + 2 * VTILEB };

    const int tid  = threadIdx.x;
    const int w    = tid >> 5;
    const int lane = tid & 31;
    const int r    = lane >> 2;
    const int c    = lane & 3;

    const int b  = blockIdx.x >> 4;
    const int q0 = (blockIdx.x & 15) << 7;
    const int qr = q0 + 16 * w + r;

    const float* Kb  = g_kr + (size_t)b * SEQ * DIMD;
    const float* Vtb = g_vt + (size_t)b * DIMD * SEQ;   // [d][s], row stride SEQ

    // prologue: stage tiles 0 and 1 (each group = K tile + V^T tile)
    ld_tile(kd[0], Kb, tid, DIMD, KPITCH * 4);
    ld_tile(vd[0], Vtb, tid, SEQ, VPITCH * 4);
    CP_COMMIT();
    ld_tile(kd[1], Kb + (size_t)KT * DIMD, tid, DIMD, KPITCH * 4);
    ld_tile(vd[1], Vtb + KT, tid, SEQ, VPITCH * 4);
    CP_COMMIT();

    uint32_t qh[32];
    load_q_frags(qh, Q, b, qr, c);

    const float inv0 = g_inv[(size_t)b * SEQ + qr];
    const float inv1 = g_inv[(size_t)b * SEQ + qr + 8];

    float cx[32];
#pragma unroll
    for (int i = 0; i < 32; i++) cx[i] = 0.f;

    int bidx = 0;
    for (int t = 0; t < NKT; t++) {
        CP_WAIT(1);
        __syncthreads();
        if (t + 2 < NKT) {
            int nb2 = bidx + 2; if (nb2 >= 3) nb2 -= 3;
            ld_tile(kd[nb2], Kb + (size_t)(t + 2) * KT * DIMD, tid, DIMD, KPITCH * 4);
            ld_tile(vd[nb2], Vtb + (size_t)(t + 2) * KT, tid, SEQ, VPITCH * 4);
            CP_COMMIT();
        }
        const float* kh = kbuf[bidx];
        const float* vt = vbuf[bidx];
        if (++bidx == 3) bidx = 0;

        float* a0p = attn_out + ((size_t)b * SEQ + qr) * SEQ + t * KT;
        float* a1p = a0p + (size_t)8 * SEQ;

#pragma unroll 2
        for (int nb = 0; nb < NB; nb++) {
            float e0 = 0.f, e1 = 0.f, e2 = 0.f, e3 = 0.f;
            float o0 = 0.f, o1 = 0.f, o2 = 0.f, o3 = 0.f;
            qk_block(e0, e1, e2, e3, o0, o1, o2, o3, kh, qh, nb, r, c);

            float p0 = __expf(e0 + o0) * inv0;
            float p1 = __expf(e1 + o1) * inv0;
            float p2 = __expf(e2 + o2) * inv1;
            float p3 = __expf(e3 + o3) * inv1;

            if (has_attn) {
                *(float2*)(a0p + nb * 8 + 2 * c) = make_float2(p0, p1);
                *(float2*)(a1p + nb * 8 + 2 * c) = make_float2(p2, p3);
            }

            // P fragments for PV (k-permutation: logical k c->2c, c+4->2c+1)
            uint32_t pa0 = f2t(p0), pa1 = f2t(p2), pa2 = f2t(p1), pa3 = f2t(p3);

            // V^T layout: b0,b1 = V[kv=nb*8+2c][d], V[kv=nb*8+2c+1][d] -> adjacent -> LDS.64
            const int vbase = r * VPITCH + nb * 8 + 2 * c;
#pragma unroll
            for (int nd = 0; nd < 8; nd++) {
                float2 bb = *(const float2*)&vt[vbase + nd * (8 * VPITCH)];
                mma8(cx[4*nd], cx[4*nd+1], cx[4*nd+2], cx[4*nd+3], pa0, pa1, pa2, pa3,
                     __float_as_uint(bb.x), __float_as_uint(bb.y));
            }
        }
        __syncthreads();
    }

    // ---- write context ----
    float* c0p = ctx_out + ((size_t)b * SEQ + qr) * DIMD;
    float* c1p = c0p + 8 * DIMD;
#pragma unroll
    for (int nd = 0; nd < 8; nd++) {
        *(float2*)(c0p + 8 * nd + 2 * c) = make_float2(cx[4*nd],   cx[4*nd+1]);
        *(float2*)(c1p + 8 * nd + 2 * c) = make_float2(cx[4*nd+2], cx[4*nd+3]);
    }
}

// ============================ launch ============================
extern "C" void kernel_launch(void* const* d_in, const int* in_sizes, int n_in,
                              void* d_out, int out_size) {
    const float* q = (const float*)d_in[0];
    const float* k = (const float*)d_in[1];
    const float* v = (const float*)d_in[2];
    float* out = (float*)d_out;

    const long long CTX_ELEMS  = (long long)BATCH * SEQ * DIMD;   // 2,097,152
    const long long ATTN_ELEMS = (long long)BATCH * SEQ * SEQ;    // 67,108,864
    float* ctx_out  = out;
    float* attn_out = out + CTX_ELEMS;
    int has_attn = ((long long)out_size >= CTX_ELEMS + ATTN_ELEMS) ? 1 : 0;

    cudaFuncSetAttribute(rowsum_kernel, cudaFuncAttributeMaxDynamicSharedMemorySize, RS_SMEM);
    cudaFuncSetAttribute(attn_kernel,   cudaFuncAttributeMaxDynamicSharedMemorySize, MAIN_SMEM);

    kround_kernel<<<(unsigned)(NELEM / 4 / 256), 256>>>(k);
    vtrans_kernel<<<dim3(SEQ / 32, DIMD / 32, BATCH), dim3(32, 8)>>>(v);
    rowsum_kernel<<<BATCH * (SEQ / QT), 256, RS_SMEM>>>(q);
    attn_kernel<<<BATCH * (SEQ / QT), 256, MAIN_SMEM>>>(q, ctx_out, attn_out, has_attn);
}